// round 14
// baseline (speedup 1.0000x reference)
#include <cuda_runtime.h>
#include <math.h>
#include <stdint.h>

#define Bsz   256
#define Lseq  200
#define Dm    128
#define HDh   64
#define MROWS (Bsz*Lseq)   // 51200

// ---------------- scratch (device globals; no allocations) ----------------
__device__ int   g_items[MROWS];
__device__ int   g_alias[MROWS];
__device__ int   g_nu[Bsz];
__device__ int   g_in_cnt[MROWS],  g_in_off[MROWS],  g_in_src[MROWS];
__device__ int   g_out_cnt[MROWS], g_out_off[MROWS], g_out_src[MROWS];
__device__ float g_Pin [MROWS*Dm];
__device__ float g_Pout[MROWS*Dm];
__device__ float g_GH  [MROWS*3*Dm];
__device__ float g_hnew[MROWS*Dm];
__device__ float g_K   [MROWS*Dm];
__device__ float g_V   [MROWS*Dm];

#define MMA8(c, a, b) \
    asm volatile("mma.sync.aligned.m16n8k8.row.col.f32.tf32.tf32.f32 " \
        "{%0,%1,%2,%3},{%4,%5,%6,%7},{%8,%9},{%0,%1,%2,%3};" \
        : "+f"((c)[0]),"+f"((c)[1]),"+f"((c)[2]),"+f"((c)[3]) \
        : "r"((a)[0]),"r"((a)[1]),"r"((a)[2]),"r"((a)[3]), \
          "r"((b)[0]),"r"((b)[1]))

#define KP    132
#define A128  (128*KP*4)
#define A64   (64*KP*4)

// ---------------- graph build: one block per batch row (+ CSR) ----------------
__global__ void build_graph_kernel(const int* __restrict__ seqs)
{
    __shared__ int s_seq[Lseq], s_sorted[Lseq], s_first[Lseq];
    __shared__ int s_items[Lseq], s_alias[Lseq];
    __shared__ int s_indeg[Lseq], s_outdeg[Lseq];
    __shared__ int s_inoff[Lseq], s_outoff[Lseq];
    __shared__ int s_infill[Lseq], s_outfill[Lseq];
    __shared__ int s_nu;
    int b = blockIdx.x, tid = threadIdx.x;

    if (tid < Lseq) {
        s_seq[tid] = seqs[b*Lseq + tid];
        s_items[tid] = 0; s_indeg[tid] = 0; s_outdeg[tid] = 0;
        s_infill[tid] = 0; s_outfill[tid] = 0;
    }
    __syncthreads();

    if (tid < Lseq) {
        int v = s_seq[tid], pos = 0;
        for (int j = 0; j < Lseq; j++) {
            int w = s_seq[j];
            pos += (w < v) || (w == v && j < tid);
        }
        s_sorted[pos] = v;
    }
    __syncthreads();
    if (tid < Lseq) s_first[tid] = (tid == 0) || (s_sorted[tid] != s_sorted[tid-1]);
    __syncthreads();
    if (tid < Lseq) {
        int c = 0;
        for (int j = 0; j <= tid; j++) c += s_first[j];
        if (s_first[tid]) s_items[c-1] = s_sorted[tid];
        if (tid == Lseq-1) s_nu = c;
    }
    __syncthreads();
    int nu = s_nu;
    if (tid == 0) g_nu[b] = nu;
    if (tid < Lseq) {
        int v = s_seq[tid], lo = 0, hi = nu;
        while (lo < hi) { int mid = (lo+hi) >> 1; if (s_items[mid] < v) lo = mid+1; else hi = mid; }
        s_alias[tid] = lo;
        g_items[b*Lseq + tid] = s_items[tid];
        g_alias[b*Lseq + tid] = lo;
    }
    __syncthreads();

    int keep = 0, u = 0, v = 0;
    if (tid < Lseq-1 && s_seq[tid+1] > 0) {
        u = s_alias[tid]; v = s_alias[tid+1];
        keep = 1;
        for (int j = 0; j < tid; j++)
            if (s_seq[j+1] > 0 && s_alias[j] == u && s_alias[j+1] == v) { keep = 0; break; }
        if (keep) { atomicAdd(&s_outdeg[u], 1); atomicAdd(&s_indeg[v], 1); }
    }
    __syncthreads();
    if (tid < Lseq) {
        int a = 0, c = 0;
        for (int j = 0; j < tid; j++) { a += s_indeg[j]; c += s_outdeg[j]; }
        s_inoff[tid] = a; s_outoff[tid] = c;
    }
    __syncthreads();
    if (keep) {
        int si = atomicAdd(&s_infill[v], 1);
        g_in_src[b*Lseq + s_inoff[v] + si] = u;
        int so = atomicAdd(&s_outfill[u], 1);
        g_out_src[b*Lseq + s_outoff[u] + so] = v;
    }
    if (tid < Lseq) {
        g_in_cnt [b*Lseq + tid] = s_indeg[tid];
        g_in_off [b*Lseq + tid] = s_inoff[tid];
        g_out_cnt[b*Lseq + tid] = s_outdeg[tid];
        g_out_off[b*Lseq + tid] = s_outoff[tid];
    }
}

// ---------------- multi-tile tf32 GEMM: batch-aligned 64-row M-tiles ----------------
struct Tile { const float* B; const float* bias; float* C; int ldc; };
struct Tiles { Tile t[5]; int n; };

__global__ void __launch_bounds__(256)
emb_gemm(const float* __restrict__ A, const int* __restrict__ rowidx,
         int axmode,
         const float* __restrict__ pos_emb, const int* __restrict__ seqs,
         const int* __restrict__ limit,
         Tiles T)
{
    extern __shared__ __align__(16) char smem[];
    uint32_t* As32 = (uint32_t*)smem;
    uint32_t* Bs32 = (uint32_t*)(smem + A64);
    int tid = threadIdx.x, wid = tid >> 5, lid = tid & 31;
    int gid = lid >> 2, tig = lid & 3;
    int mt = blockIdx.x, b = blockIdx.y;
    if (64*mt >= limit[b]) return;
    int wm = (wid & 1) << 5;
    int wn = (wid >> 1) << 5;

    for (int i = tid; i < 64*32; i += 256) {
        int r = i >> 5, c4 = (i & 31) << 2;
        int lr = min(64*mt + r, Lseq-1);
        int gr = b*Lseq + lr;
        float4 vv;
        if (axmode) {
            int a = g_alias[gr];
            const float* hp = g_hnew + (size_t)(b*Lseq + a)*Dm + c4;
            const float* pp = pos_emb + (size_t)lr*Dm + c4;
            float m = (seqs[gr] > 0) ? 1.f : 0.f;
            float4 h4 = *(const float4*)hp;
            float4 p4 = *(const float4*)pp;
            vv = make_float4((h4.x+p4.x)*m, (h4.y+p4.y)*m, (h4.z+p4.z)*m, (h4.w+p4.w)*m);
        } else {
            vv = *(const float4*)(A + (size_t)(rowidx ? rowidx[gr] : gr) * Dm + c4);
        }
        *(float4*)&As32[r*KP + c4] = vv;
    }

    for (int nt = 0; nt < T.n; nt++) {
        const Tile tl = T.t[nt];
        __syncthreads();
        for (int i = tid; i < 128*32; i += 256) {
            int r = i >> 5, c4 = (i & 31) << 2;
            *(float4*)&Bs32[r*KP + c4] = *(const float4*)(tl.B + (size_t)r*Dm + c4);
        }
        __syncthreads();

        float acc[2][4][4];
#pragma unroll
        for (int i = 0; i < 2; i++)
#pragma unroll
            for (int j = 0; j < 4; j++)
#pragma unroll
                for (int q = 0; q < 4; q++) acc[i][j][q] = 0.f;

#pragma unroll
        for (int kk = 0; kk < 16; kk++) {
            int kb = kk << 3;
            uint32_t af[2][4];
#pragma unroll
            for (int i = 0; i < 2; i++) {
                int R = wm + (i << 4) + gid;
                af[i][0] = As32[R*KP + kb + tig];
                af[i][1] = As32[(R+8)*KP + kb + tig];
                af[i][2] = As32[R*KP + kb + tig + 4];
                af[i][3] = As32[(R+8)*KP + kb + tig + 4];
            }
#pragma unroll
            for (int j = 0; j < 4; j++) {
                int Nc = wn + (j << 3) + gid;
                uint32_t bf[2];
                bf[0] = Bs32[Nc*KP + kb + tig];
                bf[1] = Bs32[Nc*KP + kb + tig + 4];
                MMA8(acc[0][j], af[0], bf);
                MMA8(acc[1][j], af[1], bf);
            }
        }

#pragma unroll
        for (int i = 0; i < 2; i++) {
            int lr0 = 64*mt + wm + (i << 4) + gid;
#pragma unroll
            for (int j = 0; j < 4; j++) {
                int ln = wn + (j << 3) + (tig << 1);
                float bx = tl.bias ? tl.bias[ln] : 0.f;
                float by = tl.bias ? tl.bias[ln+1] : 0.f;
                if (lr0 < Lseq)
                    *(float2*)&tl.C[(size_t)(b*Lseq + lr0)*tl.ldc + ln] =
                        make_float2(acc[i][j][0] + bx, acc[i][j][1] + by);
                if (lr0 + 8 < Lseq)
                    *(float2*)&tl.C[(size_t)(b*Lseq + lr0 + 8)*tl.ldc + ln] =
                        make_float2(acc[i][j][2] + bx, acc[i][j][3] + by);
            }
        }
    }
}

// ---------------- fused: CSR aggregate -> GI gemm (3 gates) -> GRU -> hnew ----------------
// 256 threads, M-tile 64, B in 12 half-N tiles (64x128 = 34KB) -> 102KB smem, 2 CTAs/SM.
__global__ void __launch_bounds__(256)
gi_gru_kernel(const float* __restrict__ w_ih,
              const float* __restrict__ b_ih,
              const float* __restrict__ b_iah, const float* __restrict__ b_oah,
              const float* __restrict__ emb)
{
    extern __shared__ __align__(16) char smem[];
    uint32_t* Bs32 = (uint32_t*)(smem + 2*A64);
    int tid = threadIdx.x, wid = tid >> 5, lid = tid & 31;
    int gid = lid >> 2, tig = lid & 3;
    int mt = blockIdx.x, b = blockIdx.y;
    if (64*mt >= g_nu[b]) return;
    int wm = (wid & 1) << 5;      // 2 m-warps x 32 rows
    int wn = (wid >> 1) << 4;     // 4 n-warps x 16 cols (within 64-col half)

    // build A segments (h_in, h_out) from CSR + Pin/Pout (raw f32)
#pragma unroll
    for (int s = 0; s < 2; s++) {
        uint32_t* As = (uint32_t*)(smem + s*A64);
        const int* cntp = s ? g_out_cnt : g_in_cnt;
        const int* offp = s ? g_out_off : g_in_off;
        const int* srcp = s ? g_out_src : g_in_src;
        const float* P  = s ? g_Pout : g_Pin;
        const float* bias = s ? b_oah : b_iah;
        for (int i = tid; i < 64*32; i += 256) {
            int r = i >> 5, c4 = (i & 31) << 2;
            int lr = min(64*mt + r, Lseq-1);
            int gr = b*Lseq + lr;
            int cnt = cntp[gr], off = offp[gr];
            float4 acc = *(const float4*)(bias + c4);
            float w = 1.0f / (float)max(cnt, 1);
            float sx = 0.f, sy = 0.f, sz = 0.f, sw = 0.f;
            int base = b*Lseq;
            for (int e = 0; e < cnt; e++) {
                int src = srcp[base + off + e];
                float4 pv = *(const float4*)(P + (size_t)(base + src)*Dm + c4);
                sx += pv.x; sy += pv.y; sz += pv.z; sw += pv.w;
            }
            acc.x += sx*w; acc.y += sy*w; acc.z += sz*w; acc.w += sw*w;
            *(float4*)&As[r*KP + c4] = acc;
        }
    }

    // acc[gate][n-half][m-sub][n-sub][quad]
    float acc[3][2][2][2][4];
#pragma unroll
    for (int g = 0; g < 3; g++)
#pragma unroll
        for (int h = 0; h < 2; h++)
#pragma unroll
            for (int i = 0; i < 2; i++)
#pragma unroll
                for (int j = 0; j < 2; j++)
#pragma unroll
                    for (int q = 0; q < 4; q++) acc[g][h][i][j][q] = 0.f;

    // 12 phases: gate g (3) x K-segment s (2) x N-half h (2)
    for (int t = 0; t < 12; t++) {
        int g = t >> 2, s = (t >> 1) & 1, h = t & 1;
        __syncthreads();
        // B half-tile: w_ih rows [g*128 + h*64, +64), K cols [s*128, +128)
        {
            const float* src = w_ih + (size_t)(g*Dm + h*HDh)*(2*Dm) + s*Dm;
            for (int i = tid; i < 64*32; i += 256) {
                int r = i >> 5, c4 = (i & 31) << 2;
                *(float4*)&Bs32[r*KP + c4] = *(const float4*)(src + (size_t)r*(2*Dm) + c4);
            }
        }
        __syncthreads();

        const uint32_t* As32 = (const uint32_t*)(smem + s*A64);
#pragma unroll
        for (int kk = 0; kk < 16; kk++) {
            int kb = kk << 3;
            uint32_t af[2][4];
#pragma unroll
            for (int i = 0; i < 2; i++) {
                int R = wm + (i << 4) + gid;
                af[i][0] = As32[R*KP + kb + tig];
                af[i][1] = As32[(R+8)*KP + kb + tig];
                af[i][2] = As32[R*KP + kb + tig + 4];
                af[i][3] = As32[(R+8)*KP + kb + tig + 4];
            }
#pragma unroll
            for (int j = 0; j < 2; j++) {
                int Nc = wn + (j << 3) + gid;
                uint32_t bf[2];
                bf[0] = Bs32[Nc*KP + kb + tig];
                bf[1] = Bs32[Nc*KP + kb + tig + 4];
                MMA8(acc[g][h][0][j], af[0], bf);
                MMA8(acc[g][h][1][j], af[1], bf);
            }
        }
    }

    // fused GRU epilogue
#pragma unroll
    for (int h = 0; h < 2; h++) {
#pragma unroll
        for (int i = 0; i < 2; i++) {
#pragma unroll
            for (int j = 0; j < 2; j++) {
                int ln = h*HDh + wn + (j << 3) + (tig << 1);
#pragma unroll
                for (int half = 0; half < 2; half++) {
                    int lr = 64*mt + wm + (i << 4) + gid + (half ? 8 : 0);
                    if (lr >= Lseq) continue;
                    int r = b*Lseq + lr;
                    int q = half << 1;
                    const float* ghr = g_GH + (size_t)r*(3*Dm);
                    float2 hr = *(const float2*)(ghr + ln);
                    float2 hi = *(const float2*)(ghr + Dm + ln);
                    float2 hn = *(const float2*)(ghr + 2*Dm + ln);
                    float2 hv = *(const float2*)(emb + (size_t)g_items[r]*Dm + ln);
                    float ir_x = acc[0][h][i][j][q]   + b_ih[ln];
                    float ir_y = acc[0][h][i][j][q+1] + b_ih[ln+1];
                    float ii_x = acc[1][h][i][j][q]   + b_ih[Dm+ln];
                    float ii_y = acc[1][h][i][j][q+1] + b_ih[Dm+ln+1];
                    float in_x = acc[2][h][i][j][q]   + b_ih[2*Dm+ln];
                    float in_y = acc[2][h][i][j][q+1] + b_ih[2*Dm+ln+1];
                    float rg_x = 1.f/(1.f + expf(-(ir_x + hr.x)));
                    float rg_y = 1.f/(1.f + expf(-(ir_y + hr.y)));
                    float z_x  = 1.f/(1.f + expf(-(ii_x + hi.x)));
                    float z_y  = 1.f/(1.f + expf(-(ii_y + hi.y)));
                    float ng_x = tanhf(in_x + rg_x*hn.x);
                    float ng_y = tanhf(in_y + rg_y*hn.y);
                    float2 o = make_float2(ng_x + z_x*(hv.x - ng_x),
                                           ng_y + z_y*(hv.y - ng_y));
                    *(float2*)&g_hnew[(size_t)r*Dm + ln] = o;
                }
            }
        }
    }
}

// ---------------- block reductions (256 threads, 8 warps) ----------------
__device__ __forceinline__ float blk_sum8(float v, float* red)
{
#pragma unroll
    for (int o = 16; o; o >>= 1) v += __shfl_xor_sync(0xffffffffu, v, o);
    __syncthreads();
    if ((threadIdx.x & 31) == 0) red[threadIdx.x >> 5] = v;
    __syncthreads();
    return red[0]+red[1]+red[2]+red[3]+red[4]+red[5]+red[6]+red[7];
}
__device__ __forceinline__ float blk_max8(float v, float* red)
{
#pragma unroll
    for (int o = 16; o; o >>= 1) v = fmaxf(v, __shfl_xor_sync(0xffffffffu, v, o));
    __syncthreads();
    if ((threadIdx.x & 31) == 0) red[threadIdx.x >> 5] = v;
    __syncthreads();
    float m = fmaxf(fmaxf(red[0], red[1]), fmaxf(red[2], red[3]));
    return fmaxf(m, fmaxf(fmaxf(red[4], red[5]), fmaxf(red[6], red[7])));
}

// warp-cooperative matvec: 8 warps x 16 rows, 2 rows/iter for ILP
__device__ __forceinline__ void warp_matvec8(const float* __restrict__ W,
                                             const float4 x4, float* __restrict__ outv,
                                             int wid, int lane)
{
#pragma unroll
    for (int rr = 0; rr < 16; rr += 2) {
        int row0 = (wid << 4) + rr;
        float4 w0 = *(const float4*)(W + (size_t)row0*Dm + (lane << 2));
        float4 w1 = *(const float4*)(W + (size_t)(row0+1)*Dm + (lane << 2));
        float s0 = w0.x*x4.x + w0.y*x4.y + w0.z*x4.z + w0.w*x4.w;
        float s1 = w1.x*x4.x + w1.y*x4.y + w1.z*x4.z + w1.w*x4.w;
#pragma unroll
        for (int o = 16; o; o >>= 1) {
            s0 += __shfl_xor_sync(0xffffffffu, s0, o);
            s1 += __shfl_xor_sync(0xffffffffu, s1, o);
        }
        if (lane == 0) { outv[row0] = s0; outv[row0+1] = s1; }
    }
}

// ---------------- per-batch tail (256 threads) ----------------
__global__ void __launch_bounds__(256)
final_kernel(const float* __restrict__ pos_emb,
             const float* __restrict__ ln1_g, const float* __restrict__ ln1_b,
             const float* __restrict__ Wq, const float* __restrict__ bq,
             const float* __restrict__ Wo, const float* __restrict__ bo,
             const float* __restrict__ ln2_g, const float* __restrict__ ln2_b,
             const float* __restrict__ W1, const float* __restrict__ b1,
             const float* __restrict__ W2, const float* __restrict__ b2,
             const float* __restrict__ lnf_g, const float* __restrict__ lnf_b,
             const int* __restrict__ lens, float* __restrict__ out)
{
    __shared__ __align__(16) float s_qin[Dm], s_q[Dm], s_v[Dm], s_f[Dm], s_tmp[Dm];
    __shared__ float s_sc[2*Lseq];
    __shared__ __align__(16) float s_part[2][Dm];
    __shared__ float red[8];
    int b = blockIdx.x, tid = threadIdx.x;
    int d = tid & 127, half = tid >> 7;
    int act = (tid < Dm);
    int lane = tid & 31, wid = tid >> 5;
    int last = lens[b] - 1;

    float ht = 0.f, xr = 0.f;
    int a_last = g_alias[b*Lseq + last];
    if (act) {
        ht = g_hnew[(size_t)(b*Lseq + a_last)*Dm + d];
        xr = ht + pos_emb[(size_t)last*Dm + d];
    }

    float mu  = blk_sum8(act ? xr : 0.f, red) * (1.f/Dm);
    float c   = xr - mu;
    float var = blk_sum8(act ? c*c : 0.f, red) * (1.f/Dm);
    float qin = c * rsqrtf(var + 1e-5f) * ln1_g[d] + ln1_b[d];
    if (act) s_qin[d] = qin;
    __syncthreads();

    {
        float4 x4 = ((const float4*)s_qin)[lane];
        warp_matvec8(Wq, x4, s_q, wid, lane);
    }
    __syncthreads();
    float qv = 0.f;
    if (act) qv = s_q[d] + bq[d];
    __syncthreads();
    if (act) s_q[d] = qv;
    for (int i = tid; i < 2*Lseq; i += 256) s_sc[i] = -1e30f;
    __syncthreads();

    float4 q4 = ((const float4*)s_q)[lane];
    for (int t = wid; t <= last; t += 8) {
        const float* kr = g_K + ((size_t)b*Lseq + t)*Dm;
        float4 k4 = *(const float4*)(kr + (lane << 2));
        float p = k4.x*q4.x + k4.y*q4.y + k4.z*q4.z + k4.w*q4.w;
        p += __shfl_xor_sync(0xffffffffu, p, 1);
        p += __shfl_xor_sync(0xffffffffu, p, 2);
        p += __shfl_xor_sync(0xffffffffu, p, 4);
        p += __shfl_xor_sync(0xffffffffu, p, 8);
        if (lane == 0)  s_sc[t]        = p * 0.125f;
        if (lane == 16) s_sc[Lseq + t] = p * 0.125f;
    }
    __syncthreads();

    float m0 = -1e30f, m1 = -1e30f;
    if (act) {
        for (int t = d; t < Lseq; t += Dm) {
            m0 = fmaxf(m0, s_sc[t]); m1 = fmaxf(m1, s_sc[Lseq+t]);
        }
    }
    m0 = blk_max8(m0, red); m1 = blk_max8(m1, red);
    float e0 = 0.f, e1 = 0.f;
    if (act) {
        for (int t = d; t < Lseq; t += Dm) {
            float a0 = expf(s_sc[t] - m0);        s_sc[t] = a0;        e0 += a0;
            float a1 = expf(s_sc[Lseq+t] - m1);   s_sc[Lseq+t] = a1;   e1 += a1;
        }
    }
    float sum0 = blk_sum8(e0, red);
    float sum1 = blk_sum8(e1, red);

    {
        int h = d >> 6;
        const float* vb = g_V + (size_t)b*Lseq*Dm + d;
        const float* sc = s_sc + h*Lseq;
        float a0 = 0.f, a1 = 0.f;
        int t = half;
        for (; t + 3 <= last; t += 4) {
            a0 += sc[t]    *vb[(size_t)t*Dm];
            a1 += sc[t+2]  *vb[(size_t)(t+2)*Dm];
        }
        for (; t <= last; t += 2) a0 += sc[t]*vb[(size_t)t*Dm];
        s_part[half][d] = a0 + a1;
    }
    __syncthreads();
    if (act) {
        float inv = 1.f / (d >= HDh ? sum1 : sum0);
        s_v[d] = (s_part[0][d] + s_part[1][d]) * inv;
    }
    __syncthreads();

    {
        float4 x4 = ((const float4*)s_v)[lane];
        warp_matvec8(Wo, x4, s_tmp, wid, lane);
    }
    __syncthreads();
    float x2 = qin + s_tmp[d] + bo[d];

    mu  = blk_sum8(act ? x2 : 0.f, red) * (1.f/Dm);
    c   = x2 - mu;
    var = blk_sum8(act ? c*c : 0.f, red) * (1.f/Dm);
    float h2 = c * rsqrtf(var + 1e-5f) * ln2_g[d] + ln2_b[d];
    __syncthreads();
    if (act) s_v[d] = h2;
    __syncthreads();

    {
        float4 x4 = ((const float4*)s_v)[lane];
        warp_matvec8(W1, x4, s_f, wid, lane);
    }
    __syncthreads();
    float fv = 0.f;
    if (act) fv = fmaxf(s_f[d] + b1[d], 0.f);
    __syncthreads();
    if (act) s_f[d] = fv;
    __syncthreads();

    {
        float4 x4 = ((const float4*)s_f)[lane];
        warp_matvec8(W2, x4, s_tmp, wid, lane);
    }
    __syncthreads();
    float x3 = h2 + b2[d] + s_tmp[d];

    mu  = blk_sum8(act ? x3 : 0.f, red) * (1.f/Dm);
    c   = x3 - mu;
    var = blk_sum8(act ? c*c : 0.f, red) * (1.f/Dm);
    float lf = c * rsqrtf(var + 1e-5f) * lnf_g[d] + lnf_b[d];
    if (act) out[b*Dm + d] = 0.6f*lf + 0.4f*ht;
}

// ---------------- host launcher ----------------
extern "C" void kernel_launch(void* const* d_in, const int* in_sizes, int n_in,
                              void* d_out, int out_size)
{
    const float* item_emb = (const float*)d_in[0];
    const float* pos_emb  = (const float*)d_in[1];
    const float* W_ei = (const float*)d_in[2];
    const float* b_ei = (const float*)d_in[3];
    const float* W_eo = (const float*)d_in[4];
    const float* b_eo = (const float*)d_in[5];
    const float* b_iah = (const float*)d_in[6];
    const float* b_oah = (const float*)d_in[7];
    const float* w_ih = (const float*)d_in[8];
    const float* b_ih = (const float*)d_in[9];
    const float* w_hh = (const float*)d_in[10];
    const float* b_hh = (const float*)d_in[11];
    const float* ln1_g = (const float*)d_in[12];
    const float* ln1_b = (const float*)d_in[13];
    const float* Wq = (const float*)d_in[14];
    const float* bq = (const float*)d_in[15];
    const float* Wk = (const float*)d_in[16];
    const float* bk = (const float*)d_in[17];
    const float* Wv = (const float*)d_in[18];
    const float* bv = (const float*)d_in[19];
    const float* Wo = (const float*)d_in[20];
    const float* bo = (const float*)d_in[21];
    const float* ln2_g = (const float*)d_in[22];
    const float* ln2_b = (const float*)d_in[23];
    const float* W1 = (const float*)d_in[24];
    const float* b1 = (const float*)d_in[25];
    const float* W2 = (const float*)d_in[26];
    const float* b2 = (const float*)d_in[27];
    const float* lnf_g = (const float*)d_in[28];
    const float* lnf_b = (const float*)d_in[29];
    const int* seqs = (const int*)d_in[30];
    const int* lens = (const int*)d_in[31];
    float* out = (float*)d_out;

    int*   items; cudaGetSymbolAddress((void**)&items, g_items);
    int*   nuarr; cudaGetSymbolAddress((void**)&nuarr, g_nu);
    float* Pin;   cudaGetSymbolAddress((void**)&Pin,  g_Pin);
    float* Pout;  cudaGetSymbolAddress((void**)&Pout, g_Pout);
    float* GH;    cudaGetSymbolAddress((void**)&GH,   g_GH);
    float* Km;    cudaGetSymbolAddress((void**)&Km,   g_K);
    float* Vm;    cudaGetSymbolAddress((void**)&Vm,   g_V);

    cudaFuncSetAttribute(emb_gemm,      cudaFuncAttributeMaxDynamicSharedMemorySize, A64 + A128);
    cudaFuncSetAttribute(gi_gru_kernel, cudaFuncAttributeMaxDynamicSharedMemorySize, 3*A64);

    build_graph_kernel<<<Bsz, 256>>>(seqs);

    dim3 gtile(4, Bsz);

    Tiles T5;
    T5.n = 5;
    T5.t[0] = {W_ei,               b_ei,           Pin,  Dm};
    T5.t[1] = {W_eo,               b_eo,           Pout, Dm};
    T5.t[2] = {w_hh,               b_hh,           GH,        3*Dm};
    T5.t[3] = {w_hh + 128*Dm,      b_hh + 128,     GH + 128,  3*Dm};
    T5.t[4] = {w_hh + 256*Dm,      b_hh + 256,     GH + 256,  3*Dm};
    emb_gemm<<<gtile, 256, A64 + A128>>>(item_emb, items, 0, nullptr, nullptr, nuarr, T5);

    gi_gru_kernel<<<gtile, 256, 3*A64>>>(w_ih, b_ih, b_iah, b_oah, item_emb);

    Tiles T2;
    T2.n = 2;
    T2.t[0] = {Wk, bk, Km, Dm};
    T2.t[1] = {Wv, bv, Vm, Dm};
    emb_gemm<<<gtile, 256, A64 + A128>>>(nullptr, nullptr, 1, pos_emb, seqs, lens, T2);

    final_kernel<<<Bsz, 256>>>(pos_emb, ln1_g, ln1_b, Wq, bq, Wo, bo,
                               ln2_g, ln2_b, W1, b1, W2, b2,
                               lnf_g, lnf_b, lens, out);
}

// round 15
// speedup vs baseline: 1.0417x; 1.0417x over previous
#include <cuda_runtime.h>
#include <math.h>
#include <stdint.h>

#define Bsz   256
#define Lseq  200
#define Dm    128
#define HDh   64
#define MROWS (Bsz*Lseq)   // 51200

// ---------------- scratch (device globals; no allocations) ----------------
__device__ int   g_items[MROWS];
__device__ int   g_alias[MROWS];
__device__ int   g_nu[Bsz];
__device__ int   g_done[Bsz];
__device__ int   g_in_cnt[MROWS],  g_in_off[MROWS],  g_in_src[MROWS];
__device__ int   g_out_cnt[MROWS], g_out_off[MROWS], g_out_src[MROWS];
__device__ float g_Pin [MROWS*Dm];
__device__ float g_Pout[MROWS*Dm];
__device__ float g_GH  [MROWS*3*Dm];
__device__ float g_hnew[MROWS*Dm];
__device__ float g_K   [MROWS*Dm];
__device__ float g_V   [MROWS*Dm];

#define MMA8(c, a, b) \
    asm volatile("mma.sync.aligned.m16n8k8.row.col.f32.tf32.tf32.f32 " \
        "{%0,%1,%2,%3},{%4,%5,%6,%7},{%8,%9},{%0,%1,%2,%3};" \
        : "+f"((c)[0]),"+f"((c)[1]),"+f"((c)[2]),"+f"((c)[3]) \
        : "r"((a)[0]),"r"((a)[1]),"r"((a)[2]),"r"((a)[3]), \
          "r"((b)[0]),"r"((b)[1]))

#define KP    132
#define A128  (128*KP*4)
#define A64   (64*KP*4)

// ---------------- graph build: one block per batch row (+ CSR) ----------------
__global__ void build_graph_kernel(const int* __restrict__ seqs)
{
    __shared__ int s_seq[Lseq], s_sorted[Lseq], s_first[Lseq];
    __shared__ int s_items[Lseq], s_alias[Lseq];
    __shared__ int s_indeg[Lseq], s_outdeg[Lseq];
    __shared__ int s_inoff[Lseq], s_outoff[Lseq];
    __shared__ int s_infill[Lseq], s_outfill[Lseq];
    __shared__ int s_nu;
    int b = blockIdx.x, tid = threadIdx.x;

    if (tid == 0) g_done[b] = 0;
    if (tid < Lseq) {
        s_seq[tid] = seqs[b*Lseq + tid];
        s_items[tid] = 0; s_indeg[tid] = 0; s_outdeg[tid] = 0;
        s_infill[tid] = 0; s_outfill[tid] = 0;
    }
    __syncthreads();

    if (tid < Lseq) {
        int v = s_seq[tid], pos = 0;
        for (int j = 0; j < Lseq; j++) {
            int w = s_seq[j];
            pos += (w < v) || (w == v && j < tid);
        }
        s_sorted[pos] = v;
    }
    __syncthreads();
    if (tid < Lseq) s_first[tid] = (tid == 0) || (s_sorted[tid] != s_sorted[tid-1]);
    __syncthreads();
    if (tid < Lseq) {
        int c = 0;
        for (int j = 0; j <= tid; j++) c += s_first[j];
        if (s_first[tid]) s_items[c-1] = s_sorted[tid];
        if (tid == Lseq-1) s_nu = c;
    }
    __syncthreads();
    int nu = s_nu;
    if (tid == 0) g_nu[b] = nu;
    if (tid < Lseq) {
        int v = s_seq[tid], lo = 0, hi = nu;
        while (lo < hi) { int mid = (lo+hi) >> 1; if (s_items[mid] < v) lo = mid+1; else hi = mid; }
        s_alias[tid] = lo;
        g_items[b*Lseq + tid] = s_items[tid];
        g_alias[b*Lseq + tid] = lo;
    }
    __syncthreads();

    int keep = 0, u = 0, v = 0;
    if (tid < Lseq-1 && s_seq[tid+1] > 0) {
        u = s_alias[tid]; v = s_alias[tid+1];
        keep = 1;
        for (int j = 0; j < tid; j++)
            if (s_seq[j+1] > 0 && s_alias[j] == u && s_alias[j+1] == v) { keep = 0; break; }
        if (keep) { atomicAdd(&s_outdeg[u], 1); atomicAdd(&s_indeg[v], 1); }
    }
    __syncthreads();
    if (tid < Lseq) {
        int a = 0, c = 0;
        for (int j = 0; j < tid; j++) { a += s_indeg[j]; c += s_outdeg[j]; }
        s_inoff[tid] = a; s_outoff[tid] = c;
    }
    __syncthreads();
    if (keep) {
        int si = atomicAdd(&s_infill[v], 1);
        g_in_src[b*Lseq + s_inoff[v] + si] = u;
        int so = atomicAdd(&s_outfill[u], 1);
        g_out_src[b*Lseq + s_outoff[u] + so] = v;
    }
    if (tid < Lseq) {
        g_in_cnt [b*Lseq + tid] = s_indeg[tid];
        g_in_off [b*Lseq + tid] = s_inoff[tid];
        g_out_cnt[b*Lseq + tid] = s_outdeg[tid];
        g_out_off[b*Lseq + tid] = s_outoff[tid];
    }
}

// ---------------- multi-tile tf32 GEMM: batch-aligned 64-row M-tiles ----------------
struct Tile { const float* B; const float* bias; float* C; int ldc; };
struct Tiles { Tile t[5]; int n; };

__global__ void __launch_bounds__(256)
emb_gemm(const float* __restrict__ A, const int* __restrict__ rowidx,
         const int* __restrict__ limit,
         Tiles T)
{
    extern __shared__ __align__(16) char smem[];
    uint32_t* As32 = (uint32_t*)smem;
    uint32_t* Bs32 = (uint32_t*)(smem + A64);
    int tid = threadIdx.x, wid = tid >> 5, lid = tid & 31;
    int gid = lid >> 2, tig = lid & 3;
    int mt = blockIdx.x, b = blockIdx.y;
    if (64*mt >= limit[b]) return;
    int wm = (wid & 1) << 5;
    int wn = (wid >> 1) << 5;

    for (int i = tid; i < 64*32; i += 256) {
        int r = i >> 5, c4 = (i & 31) << 2;
        int lr = min(64*mt + r, Lseq-1);
        int gr = b*Lseq + lr;
        float4 vv = *(const float4*)(A + (size_t)(rowidx ? rowidx[gr] : gr) * Dm + c4);
        *(float4*)&As32[r*KP + c4] = vv;
    }

    for (int nt = 0; nt < T.n; nt++) {
        const Tile tl = T.t[nt];
        __syncthreads();
        for (int i = tid; i < 128*32; i += 256) {
            int r = i >> 5, c4 = (i & 31) << 2;
            *(float4*)&Bs32[r*KP + c4] = *(const float4*)(tl.B + (size_t)r*Dm + c4);
        }
        __syncthreads();

        float acc[2][4][4];
#pragma unroll
        for (int i = 0; i < 2; i++)
#pragma unroll
            for (int j = 0; j < 4; j++)
#pragma unroll
                for (int q = 0; q < 4; q++) acc[i][j][q] = 0.f;

#pragma unroll
        for (int kk = 0; kk < 16; kk++) {
            int kb = kk << 3;
            uint32_t af[2][4];
#pragma unroll
            for (int i = 0; i < 2; i++) {
                int R = wm + (i << 4) + gid;
                af[i][0] = As32[R*KP + kb + tig];
                af[i][1] = As32[(R+8)*KP + kb + tig];
                af[i][2] = As32[R*KP + kb + tig + 4];
                af[i][3] = As32[(R+8)*KP + kb + tig + 4];
            }
#pragma unroll
            for (int j = 0; j < 4; j++) {
                int Nc = wn + (j << 3) + gid;
                uint32_t bf[2];
                bf[0] = Bs32[Nc*KP + kb + tig];
                bf[1] = Bs32[Nc*KP + kb + tig + 4];
                MMA8(acc[0][j], af[0], bf);
                MMA8(acc[1][j], af[1], bf);
            }
        }

#pragma unroll
        for (int i = 0; i < 2; i++) {
            int lr0 = 64*mt + wm + (i << 4) + gid;
#pragma unroll
            for (int j = 0; j < 4; j++) {
                int ln = wn + (j << 3) + (tig << 1);
                float bx = tl.bias ? tl.bias[ln] : 0.f;
                float by = tl.bias ? tl.bias[ln+1] : 0.f;
                if (lr0 < Lseq)
                    *(float2*)&tl.C[(size_t)(b*Lseq + lr0)*tl.ldc + ln] =
                        make_float2(acc[i][j][0] + bx, acc[i][j][1] + by);
                if (lr0 + 8 < Lseq)
                    *(float2*)&tl.C[(size_t)(b*Lseq + lr0 + 8)*tl.ldc + ln] =
                        make_float2(acc[i][j][2] + bx, acc[i][j][3] + by);
            }
        }
    }
}

// ---------------- fused: CSR aggregate -> GI gemm (3 gates) -> GRU -> hnew (R13) ----------------
__global__ void __launch_bounds__(512)
gi_gru_kernel(const float* __restrict__ w_ih,
              const float* __restrict__ b_ih,
              const float* __restrict__ b_iah, const float* __restrict__ b_oah,
              const float* __restrict__ emb)
{
    extern __shared__ __align__(16) char smem[];
    uint32_t* Bs32 = (uint32_t*)(smem + 2*A64);
    int tid = threadIdx.x, wid = tid >> 5, lid = tid & 31;
    int gid = lid >> 2, tig = lid & 3;
    int mt = blockIdx.x, b = blockIdx.y;
    if (64*mt >= g_nu[b]) return;
    int wm = (wid & 1) << 5;
    int wn = (wid >> 1) << 4;

#pragma unroll
    for (int s = 0; s < 2; s++) {
        uint32_t* As = (uint32_t*)(smem + s*A64);
        const int* cntp = s ? g_out_cnt : g_in_cnt;
        const int* offp = s ? g_out_off : g_in_off;
        const int* srcp = s ? g_out_src : g_in_src;
        const float* P  = s ? g_Pout : g_Pin;
        const float* bias = s ? b_oah : b_iah;
        for (int i = tid; i < 64*32; i += 512) {
            int r = i >> 5, c4 = (i & 31) << 2;
            int lr = min(64*mt + r, Lseq-1);
            int gr = b*Lseq + lr;
            int cnt = cntp[gr], off = offp[gr];
            float4 acc = *(const float4*)(bias + c4);
            float w = 1.0f / (float)max(cnt, 1);
            float sx = 0.f, sy = 0.f, sz = 0.f, sw = 0.f;
            int base = b*Lseq;
            for (int e = 0; e < cnt; e++) {
                int src = srcp[base + off + e];
                float4 pv = *(const float4*)(P + (size_t)(base + src)*Dm + c4);
                sx += pv.x; sy += pv.y; sz += pv.z; sw += pv.w;
            }
            acc.x += sx*w; acc.y += sy*w; acc.z += sz*w; acc.w += sw*w;
            *(float4*)&As[r*KP + c4] = acc;
        }
    }

    float acc[3][2][2][4];
#pragma unroll
    for (int g = 0; g < 3; g++)
#pragma unroll
        for (int i = 0; i < 2; i++)
#pragma unroll
            for (int j = 0; j < 2; j++)
#pragma unroll
                for (int q = 0; q < 4; q++) acc[g][i][j][q] = 0.f;

#pragma unroll
    for (int g = 0; g < 3; g++) {
#pragma unroll
        for (int s = 0; s < 2; s++) {
            __syncthreads();
            for (int i = tid; i < 128*32; i += 512) {
                int r = i >> 5, c4 = (i & 31) << 2;
                *(float4*)&Bs32[r*KP + c4] =
                    *(const float4*)(w_ih + (size_t)(g*Dm + r)*(2*Dm) + s*Dm + c4);
            }
            __syncthreads();

            const uint32_t* As32 = (const uint32_t*)(smem + s*A64);
#pragma unroll
            for (int kk = 0; kk < 16; kk++) {
                int kb = kk << 3;
                uint32_t af[2][4];
#pragma unroll
                for (int i = 0; i < 2; i++) {
                    int R = wm + (i << 4) + gid;
                    af[i][0] = As32[R*KP + kb + tig];
                    af[i][1] = As32[(R+8)*KP + kb + tig];
                    af[i][2] = As32[R*KP + kb + tig + 4];
                    af[i][3] = As32[(R+8)*KP + kb + tig + 4];
                }
#pragma unroll
                for (int j = 0; j < 2; j++) {
                    int Nc = wn + (j << 3) + gid;
                    uint32_t bf[2];
                    bf[0] = Bs32[Nc*KP + kb + tig];
                    bf[1] = Bs32[Nc*KP + kb + tig + 4];
                    MMA8(acc[g][0][j], af[0], bf);
                    MMA8(acc[g][1][j], af[1], bf);
                }
            }
        }
    }

#pragma unroll
    for (int i = 0; i < 2; i++) {
#pragma unroll
        for (int j = 0; j < 2; j++) {
            int ln = wn + (j << 3) + (tig << 1);
#pragma unroll
            for (int half = 0; half < 2; half++) {
                int lr = 64*mt + wm + (i << 4) + gid + (half ? 8 : 0);
                if (lr >= Lseq) continue;
                int r = b*Lseq + lr;
                int q = half << 1;
                const float* ghr = g_GH + (size_t)r*(3*Dm);
                float2 hr = *(const float2*)(ghr + ln);
                float2 hi = *(const float2*)(ghr + Dm + ln);
                float2 hn = *(const float2*)(ghr + 2*Dm + ln);
                float2 hv = *(const float2*)(emb + (size_t)g_items[r]*Dm + ln);
                float ir_x = acc[0][i][j][q]   + b_ih[ln];
                float ir_y = acc[0][i][j][q+1] + b_ih[ln+1];
                float ii_x = acc[1][i][j][q]   + b_ih[Dm+ln];
                float ii_y = acc[1][i][j][q+1] + b_ih[Dm+ln+1];
                float in_x = acc[2][i][j][q]   + b_ih[2*Dm+ln];
                float in_y = acc[2][i][j][q+1] + b_ih[2*Dm+ln+1];
                float rg_x = 1.f/(1.f + expf(-(ir_x + hr.x)));
                float rg_y = 1.f/(1.f + expf(-(ir_y + hr.y)));
                float z_x  = 1.f/(1.f + expf(-(ii_x + hi.x)));
                float z_y  = 1.f/(1.f + expf(-(ii_y + hi.y)));
                float ng_x = tanhf(in_x + rg_x*hn.x);
                float ng_y = tanhf(in_y + rg_y*hn.y);
                float2 o = make_float2(ng_x + z_x*(hv.x - ng_x),
                                       ng_y + z_y*(hv.y - ng_y));
                *(float2*)&g_hnew[(size_t)r*Dm + ln] = o;
            }
        }
    }
}

// ---------------- block reductions (256 threads, 8 warps) ----------------
__device__ __forceinline__ float blk_sum8(float v, float* red)
{
#pragma unroll
    for (int o = 16; o; o >>= 1) v += __shfl_xor_sync(0xffffffffu, v, o);
    __syncthreads();
    if ((threadIdx.x & 31) == 0) red[threadIdx.x >> 5] = v;
    __syncthreads();
    return red[0]+red[1]+red[2]+red[3]+red[4]+red[5]+red[6]+red[7];
}
__device__ __forceinline__ float blk_max8(float v, float* red)
{
#pragma unroll
    for (int o = 16; o; o >>= 1) v = fmaxf(v, __shfl_xor_sync(0xffffffffu, v, o));
    __syncthreads();
    if ((threadIdx.x & 31) == 0) red[threadIdx.x >> 5] = v;
    __syncthreads();
    float m = fmaxf(fmaxf(red[0], red[1]), fmaxf(red[2], red[3]));
    return fmaxf(m, fmaxf(fmaxf(red[4], red[5]), fmaxf(red[6], red[7])));
}

__device__ __forceinline__ void warp_matvec8(const float* __restrict__ W,
                                             const float4 x4, float* __restrict__ outv,
                                             int wid, int lane)
{
#pragma unroll
    for (int rr = 0; rr < 16; rr += 2) {
        int row0 = (wid << 4) + rr;
        float4 w0 = *(const float4*)(W + (size_t)row0*Dm + (lane << 2));
        float4 w1 = *(const float4*)(W + (size_t)(row0+1)*Dm + (lane << 2));
        float s0 = w0.x*x4.x + w0.y*x4.y + w0.z*x4.z + w0.w*x4.w;
        float s1 = w1.x*x4.x + w1.y*x4.y + w1.z*x4.z + w1.w*x4.w;
#pragma unroll
        for (int o = 16; o; o >>= 1) {
            s0 += __shfl_xor_sync(0xffffffffu, s0, o);
            s1 += __shfl_xor_sync(0xffffffffu, s1, o);
        }
        if (lane == 0) { outv[row0] = s0; outv[row0+1] = s1; }
    }
}

// ---------------- fused K/V GEMM + per-batch attention tail ----------------
__global__ void __launch_bounds__(256)
kv_final_kernel(const float* __restrict__ pos_emb, const int* __restrict__ seqs,
                const int* __restrict__ lens,
                const float* __restrict__ Wk, const float* __restrict__ bk,
                const float* __restrict__ Wv, const float* __restrict__ bv,
                const float* __restrict__ ln1_g, const float* __restrict__ ln1_b,
                const float* __restrict__ Wq, const float* __restrict__ bq,
                const float* __restrict__ Wo, const float* __restrict__ bo,
                const float* __restrict__ ln2_g, const float* __restrict__ ln2_b,
                const float* __restrict__ W1, const float* __restrict__ b1,
                const float* __restrict__ W2, const float* __restrict__ b2,
                const float* __restrict__ lnf_g, const float* __restrict__ lnf_b,
                float* __restrict__ out)
{
    extern __shared__ __align__(16) char smem[];
    uint32_t* As32 = (uint32_t*)smem;
    uint32_t* Bs32 = (uint32_t*)(smem + A64);
    __shared__ __align__(16) float s_qin[Dm], s_q[Dm], s_v[Dm], s_f[Dm], s_tmp[Dm];
    __shared__ float s_sc[2*Lseq];
    __shared__ __align__(16) float s_part[2][Dm];
    __shared__ float red[8];
    __shared__ int s_last_flag;

    int tid = threadIdx.x, wid = tid >> 5, lid = tid & 31;
    int gid = lid >> 2, tig = lid & 3;
    int mt = blockIdx.x, b = blockIdx.y;
    int len = lens[b];
    if (64*mt >= len) return;
    int wm = (wid & 1) << 5;
    int wn = (wid >> 1) << 5;

    // ---- K/V GEMM phase ----
    for (int i = tid; i < 64*32; i += 256) {
        int r = i >> 5, c4 = (i & 31) << 2;
        int lr = min(64*mt + r, Lseq-1);
        int gr = b*Lseq + lr;
        int a = g_alias[gr];
        const float* hp = g_hnew + (size_t)(b*Lseq + a)*Dm + c4;
        const float* pp = pos_emb + (size_t)lr*Dm + c4;
        float m = (seqs[gr] > 0) ? 1.f : 0.f;
        float4 h4 = *(const float4*)hp;
        float4 p4 = *(const float4*)pp;
        *(float4*)&As32[r*KP + c4] =
            make_float4((h4.x+p4.x)*m, (h4.y+p4.y)*m, (h4.z+p4.z)*m, (h4.w+p4.w)*m);
    }

    for (int nt = 0; nt < 2; nt++) {
        const float* Bw   = nt ? Wv : Wk;
        const float* bias = nt ? bv : bk;
        float* C          = nt ? g_V : g_K;
        __syncthreads();
        for (int i = tid; i < 128*32; i += 256) {
            int r = i >> 5, c4 = (i & 31) << 2;
            *(float4*)&Bs32[r*KP + c4] = *(const float4*)(Bw + (size_t)r*Dm + c4);
        }
        __syncthreads();

        float acc[2][4][4];
#pragma unroll
        for (int i = 0; i < 2; i++)
#pragma unroll
            for (int j = 0; j < 4; j++)
#pragma unroll
                for (int q = 0; q < 4; q++) acc[i][j][q] = 0.f;

#pragma unroll
        for (int kk = 0; kk < 16; kk++) {
            int kb = kk << 3;
            uint32_t af[2][4];
#pragma unroll
            for (int i = 0; i < 2; i++) {
                int R = wm + (i << 4) + gid;
                af[i][0] = As32[R*KP + kb + tig];
                af[i][1] = As32[(R+8)*KP + kb + tig];
                af[i][2] = As32[R*KP + kb + tig + 4];
                af[i][3] = As32[(R+8)*KP + kb + tig + 4];
            }
#pragma unroll
            for (int j = 0; j < 4; j++) {
                int Nc = wn + (j << 3) + gid;
                uint32_t bf[2];
                bf[0] = Bs32[Nc*KP + kb + tig];
                bf[1] = Bs32[Nc*KP + kb + tig + 4];
                MMA8(acc[0][j], af[0], bf);
                MMA8(acc[1][j], af[1], bf);
            }
        }

#pragma unroll
        for (int i = 0; i < 2; i++) {
            int lr0 = 64*mt + wm + (i << 4) + gid;
#pragma unroll
            for (int j = 0; j < 4; j++) {
                int ln = wn + (j << 3) + (tig << 1);
                float bx = bias[ln], by = bias[ln+1];
                if (lr0 < Lseq)
                    *(float2*)&C[(size_t)(b*Lseq + lr0)*Dm + ln] =
                        make_float2(acc[i][j][0] + bx, acc[i][j][1] + by);
                if (lr0 + 8 < Lseq)
                    *(float2*)&C[(size_t)(b*Lseq + lr0 + 8)*Dm + ln] =
                        make_float2(acc[i][j][2] + bx, acc[i][j][3] + by);
            }
        }
    }

    // ---- completion counter: last live block of batch b runs the tail ----
    __threadfence();
    __syncthreads();
    if (tid == 0) {
        int live = (len + 63) >> 6;
        int old = atomicAdd(&g_done[b], 1);
        s_last_flag = (old == live - 1);
    }
    __syncthreads();
    if (!s_last_flag) return;
    __threadfence();   // acquire: other blocks' K/V stores visible

    // ---- per-batch attention + FFN tail (256 threads) ----
    int d = tid & 127, half = tid >> 7;
    int act = (tid < Dm);
    int lane = lid;
    int last = len - 1;

    float ht = 0.f, xr = 0.f;
    int a_last = g_alias[b*Lseq + last];
    if (act) {
        ht = g_hnew[(size_t)(b*Lseq + a_last)*Dm + d];
        xr = ht + pos_emb[(size_t)last*Dm + d];
    }

    float mu  = blk_sum8(act ? xr : 0.f, red) * (1.f/Dm);
    float c   = xr - mu;
    float var = blk_sum8(act ? c*c : 0.f, red) * (1.f/Dm);
    float qin = c * rsqrtf(var + 1e-5f) * ln1_g[d] + ln1_b[d];
    if (act) s_qin[d] = qin;
    __syncthreads();

    {
        float4 x4 = ((const float4*)s_qin)[lane];
        warp_matvec8(Wq, x4, s_q, wid, lane);
    }
    __syncthreads();
    float qv = 0.f;
    if (act) qv = s_q[d] + bq[d];
    __syncthreads();
    if (act) s_q[d] = qv;
    for (int i = tid; i < 2*Lseq; i += 256) s_sc[i] = -1e30f;
    __syncthreads();

    float4 q4 = ((const float4*)s_q)[lane];
    for (int t = wid; t <= last; t += 8) {
        const float* kr = g_K + ((size_t)b*Lseq + t)*Dm;
        float4 k4 = *(const float4*)(kr + (lane << 2));
        float p = k4.x*q4.x + k4.y*q4.y + k4.z*q4.z + k4.w*q4.w;
        p += __shfl_xor_sync(0xffffffffu, p, 1);
        p += __shfl_xor_sync(0xffffffffu, p, 2);
        p += __shfl_xor_sync(0xffffffffu, p, 4);
        p += __shfl_xor_sync(0xffffffffu, p, 8);
        if (lane == 0)  s_sc[t]        = p * 0.125f;
        if (lane == 16) s_sc[Lseq + t] = p * 0.125f;
    }
    __syncthreads();

    float m0 = -1e30f, m1 = -1e30f;
    if (act) {
        for (int t = d; t < Lseq; t += Dm) {
            m0 = fmaxf(m0, s_sc[t]); m1 = fmaxf(m1, s_sc[Lseq+t]);
        }
    }
    m0 = blk_max8(m0, red); m1 = blk_max8(m1, red);
    float e0 = 0.f, e1 = 0.f;
    if (act) {
        for (int t = d; t < Lseq; t += Dm) {
            float a0 = expf(s_sc[t] - m0);        s_sc[t] = a0;        e0 += a0;
            float a1 = expf(s_sc[Lseq+t] - m1);   s_sc[Lseq+t] = a1;   e1 += a1;
        }
    }
    float sum0 = blk_sum8(e0, red);
    float sum1 = blk_sum8(e1, red);

    {
        int h = d >> 6;
        const float* vb = g_V + (size_t)b*Lseq*Dm + d;
        const float* sc = s_sc + h*Lseq;
        float a0 = 0.f, a1 = 0.f;
        int t = half;
        for (; t + 3 <= last; t += 4) {
            a0 += sc[t]    *vb[(size_t)t*Dm];
            a1 += sc[t+2]  *vb[(size_t)(t+2)*Dm];
        }
        for (; t <= last; t += 2) a0 += sc[t]*vb[(size_t)t*Dm];
        s_part[half][d] = a0 + a1;
    }
    __syncthreads();
    if (act) {
        float inv = 1.f / (d >= HDh ? sum1 : sum0);
        s_v[d] = (s_part[0][d] + s_part[1][d]) * inv;
    }
    __syncthreads();

    {
        float4 x4 = ((const float4*)s_v)[lane];
        warp_matvec8(Wo, x4, s_tmp, wid, lane);
    }
    __syncthreads();
    float x2 = qin + s_tmp[d] + bo[d];

    mu  = blk_sum8(act ? x2 : 0.f, red) * (1.f/Dm);
    c   = x2 - mu;
    var = blk_sum8(act ? c*c : 0.f, red) * (1.f/Dm);
    float h2 = c * rsqrtf(var + 1e-5f) * ln2_g[d] + ln2_b[d];
    __syncthreads();
    if (act) s_v[d] = h2;
    __syncthreads();

    {
        float4 x4 = ((const float4*)s_v)[lane];
        warp_matvec8(W1, x4, s_f, wid, lane);
    }
    __syncthreads();
    float fv = 0.f;
    if (act) fv = fmaxf(s_f[d] + b1[d], 0.f);
    __syncthreads();
    if (act) s_f[d] = fv;
    __syncthreads();

    {
        float4 x4 = ((const float4*)s_f)[lane];
        warp_matvec8(W2, x4, s_tmp, wid, lane);
    }
    __syncthreads();
    float x3 = h2 + b2[d] + s_tmp[d];

    mu  = blk_sum8(act ? x3 : 0.f, red) * (1.f/Dm);
    c   = x3 - mu;
    var = blk_sum8(act ? c*c : 0.f, red) * (1.f/Dm);
    float lf = c * rsqrtf(var + 1e-5f) * lnf_g[d] + lnf_b[d];
    if (act) out[b*Dm + d] = 0.6f*lf + 0.4f*ht;
}

// ---------------- host launcher ----------------
extern "C" void kernel_launch(void* const* d_in, const int* in_sizes, int n_in,
                              void* d_out, int out_size)
{
    const float* item_emb = (const float*)d_in[0];
    const float* pos_emb  = (const float*)d_in[1];
    const float* W_ei = (const float*)d_in[2];
    const float* b_ei = (const float*)d_in[3];
    const float* W_eo = (const float*)d_in[4];
    const float* b_eo = (const float*)d_in[5];
    const float* b_iah = (const float*)d_in[6];
    const float* b_oah = (const float*)d_in[7];
    const float* w_ih = (const float*)d_in[8];
    const float* b_ih = (const float*)d_in[9];
    const float* w_hh = (const float*)d_in[10];
    const float* b_hh = (const float*)d_in[11];
    const float* ln1_g = (const float*)d_in[12];
    const float* ln1_b = (const float*)d_in[13];
    const float* Wq = (const float*)d_in[14];
    const float* bq = (const float*)d_in[15];
    const float* Wk = (const float*)d_in[16];
    const float* bk = (const float*)d_in[17];
    const float* Wv = (const float*)d_in[18];
    const float* bv = (const float*)d_in[19];
    const float* Wo = (const float*)d_in[20];
    const float* bo = (const float*)d_in[21];
    const float* ln2_g = (const float*)d_in[22];
    const float* ln2_b = (const float*)d_in[23];
    const float* W1 = (const float*)d_in[24];
    const float* b1 = (const float*)d_in[25];
    const float* W2 = (const float*)d_in[26];
    const float* b2 = (const float*)d_in[27];
    const float* lnf_g = (const float*)d_in[28];
    const float* lnf_b = (const float*)d_in[29];
    const int* seqs = (const int*)d_in[30];
    const int* lens = (const int*)d_in[31];
    float* out = (float*)d_out;

    int*   items; cudaGetSymbolAddress((void**)&items, g_items);
    int*   nuarr; cudaGetSymbolAddress((void**)&nuarr, g_nu);
    float* Pin;   cudaGetSymbolAddress((void**)&Pin,  g_Pin);
    float* Pout;  cudaGetSymbolAddress((void**)&Pout, g_Pout);
    float* GH;    cudaGetSymbolAddress((void**)&GH,   g_GH);

    cudaFuncSetAttribute(emb_gemm,        cudaFuncAttributeMaxDynamicSharedMemorySize, A64 + A128);
    cudaFuncSetAttribute(gi_gru_kernel,   cudaFuncAttributeMaxDynamicSharedMemorySize, 2*A64 + A128);
    cudaFuncSetAttribute(kv_final_kernel, cudaFuncAttributeMaxDynamicSharedMemorySize, A64 + A128);

    build_graph_kernel<<<Bsz, 256>>>(seqs);

    dim3 gtile(4, Bsz);

    Tiles T5;
    T5.n = 5;
    T5.t[0] = {W_ei,               b_ei,           Pin,  Dm};
    T5.t[1] = {W_eo,               b_eo,           Pout, Dm};
    T5.t[2] = {w_hh,               b_hh,           GH,        3*Dm};
    T5.t[3] = {w_hh + 128*Dm,      b_hh + 128,     GH + 128,  3*Dm};
    T5.t[4] = {w_hh + 256*Dm,      b_hh + 256,     GH + 256,  3*Dm};
    emb_gemm<<<gtile, 256, A64 + A128>>>(item_emb, items, nuarr, T5);

    gi_gru_kernel<<<gtile, 512, 2*A64 + A128>>>(w_ih, b_ih, b_iah, b_oah, item_emb);

    kv_final_kernel<<<gtile, 256, A64 + A128>>>(pos_emb, seqs, lens,
                                                Wk, bk, Wv, bv,
                                                ln1_g, ln1_b, Wq, bq, Wo, bo,
                                                ln2_g, ln2_b, W1, b1, W2, b2,
                                                lnf_g, lnf_b, out);
}